// round 8
// baseline (speedup 1.0000x reference)
#include <cuda_runtime.h>

// FWHT over last axis, DIM=4096 = 16*16*16, fp32, scale 1/64.
// Three in-register H16 passes over base-16 digits (n2,n1,n0), two smem
// exchanges. One CTA (256 threads) per row, 16 floats/thread.
//
// Shared layout (word units):
//   P(n2,n1,n0) = 272*n2 + 16*n1 + 4*((n0>>2) ^ ((n1>>1)&3)) + (n0&3)
// - 272 = 16*17 word stride per n2 block: 272 mod 32 = 16 -> n2 parity
//   splits bank halves.
// - float4-granularity XOR swizzle ((n1>>1)&3) keeps phase-A STS.128
//   conflict-free per quarter-warp and phases B/C conflict-free per warp
//   (16*parity(n2 or k) + bijective low-4 from the XOR).
//
// Exchange A (phase A write -> phase B read) stays inside an n2-group
// (16 threads, half-warp), so only __syncwarp() is needed there; the single
// __syncthreads() covers the B->C exchange which crosses the whole CTA.

#define FWHT_DIM 4096

__device__ __forceinline__ void h16(float (&v)[16]) {
#pragma unroll
    for (int h = 1; h < 16; h <<= 1) {
#pragma unroll
        for (int i = 0; i < 16; i++) {
            if (!(i & h)) {
                float a = v[i];
                float b = v[i + h];
                v[i]     = a + b;
                v[i + h] = a - b;
            }
        }
    }
}

__global__ __launch_bounds__(256, 7)
void fwht4096_kernel(const float* __restrict__ x, float* __restrict__ y) {
    __shared__ float s[16 * 272];   // 17408 B

    const int t = threadIdx.x;                    // 0..255
    const size_t row = (size_t)blockIdx.x * FWHT_DIM;

    float v[16];

    // ---- Load: 16 contiguous floats (digit n0), 4x LDG.128 ----
    {
        const float4* __restrict__ p =
            reinterpret_cast<const float4*>(x + row) + t * 4;
#pragma unroll
        for (int j = 0; j < 4; j++) {
            float4 f = __ldcs(p + j);
            v[4 * j + 0] = f.x;
            v[4 * j + 1] = f.y;
            v[4 * j + 2] = f.z;
            v[4 * j + 3] = f.w;
        }
    }

    // H16 over n0
    h16(v);

    // ---- Phase A: thread (n2 = t>>4, n1 = t&15) scatters 4x STS.128 ----
    {
        const int n1 = t & 15;
        const int c  = (n1 >> 1) & 3;
        float4* b4 = reinterpret_cast<float4*>(s + (t >> 4) * 272 + n1 * 16);
#pragma unroll
        for (int a = 0; a < 4; a++)
            b4[a ^ c] = make_float4(v[4 * a], v[4 * a + 1],
                                    v[4 * a + 2], v[4 * a + 3]);
    }
    __syncwarp();   // exchange A is within a half-warp (n2-group)

    // ---- Phase B: thread (n2 = t>>4, n0 = t&15) gathers n1 = k ----
    {
        const int n0 = t & 15;
        const int g  = n0 >> 2;
        // addr(k) = n2*272 + 16k + 4*(g ^ ((k>>1)&3)) + (n0&3)
        float* base = s + (t >> 4) * 272 + (n0 & 3);
#pragma unroll
        for (int k = 0; k < 16; k++)
            v[k] = base[16 * k + 4 * (g ^ ((k >> 1) & 3))];

        h16(v);   // H16 over n1

#pragma unroll
        for (int k = 0; k < 16; k++)
            base[16 * k + 4 * (g ^ ((k >> 1) & 3))] = v[k];
    }
    __syncthreads();   // exchange B crosses the whole CTA

    // ---- Phase C: thread (n1' = t>>4, n0' = t&15) gathers n2 = k ----
    {
        const int n1 = t >> 4;
        const int n0 = t & 15;
        const float* base = s + n1 * 16
                              + 4 * ((n0 >> 2) ^ ((n1 >> 1) & 3)) + (n0 & 3);
#pragma unroll
        for (int k = 0; k < 16; k++)
            v[k] = base[272 * k];

        h16(v);   // H16 over n2

        const float sc = 0.015625f;   // 1/64
        float* __restrict__ yr = y + row + 16 * n1 + n0;
#pragma unroll
        for (int k = 0; k < 16; k++)
            __stcs(yr + 256 * k, v[k] * sc);   // 128B-coalesced per warp instr
    }
}

extern "C" void kernel_launch(void* const* d_in, const int* in_sizes, int n_in,
                              void* d_out, int out_size) {
    (void)n_in; (void)out_size;
    const float* x = (const float*)d_in[0];
    float* y = (float*)d_out;
    const int rows = in_sizes[0] / FWHT_DIM;   // 16384
    fwht4096_kernel<<<rows, 256>>>(x, y);
}

// round 9
// speedup vs baseline: 1.0044x; 1.0044x over previous
#include <cuda_runtime.h>

// FWHT over last axis, DIM=4096 = 16*16*16, fp32, scale 1/64.
// Three in-register H16 passes over base-16 digits (n2,n1,n0), two smem
// exchanges. One CTA (256 threads) per row, 16 floats/thread.
//
// Shared layout (word units):
//   P(n2,n1,n0) = 272*n2 + 16*n1 + 4*((n0>>2) ^ ((n1>>1)&3)) + (n0&3)
// - 272 = 16*17 word stride per n2 block: 272 mod 32 = 16 -> n2 parity
//   splits bank halves.
// - float4-granularity XOR swizzle ((n1>>1)&3) keeps phase-A STS.128
//   conflict-free per quarter-warp and phases B/C conflict-free per warp
//   (16*parity(n2 or k) + bijective low-4 from the XOR).
//
// Exchange A (phase A write -> phase B read) stays inside an n2-group
// (16 threads, half-warp), so only __syncwarp() is needed there; the single
// __syncthreads() covers the B->C exchange which crosses the whole CTA.

#define FWHT_DIM 4096

__device__ __forceinline__ void h16(float (&v)[16]) {
#pragma unroll
    for (int h = 1; h < 16; h <<= 1) {
#pragma unroll
        for (int i = 0; i < 16; i++) {
            if (!(i & h)) {
                float a = v[i];
                float b = v[i + h];
                v[i]     = a + b;
                v[i + h] = a - b;
            }
        }
    }
}

__global__ __launch_bounds__(256, 7)
void fwht4096_kernel(const float* __restrict__ x, float* __restrict__ y) {
    __shared__ float s[16 * 272];   // 17408 B

    const int t = threadIdx.x;                    // 0..255
    const size_t row = (size_t)blockIdx.x * FWHT_DIM;

    float v[16];

    // ---- Load: 16 contiguous floats (digit n0), 4x LDG.128 ----
    {
        const float4* __restrict__ p =
            reinterpret_cast<const float4*>(x + row) + t * 4;
#pragma unroll
        for (int j = 0; j < 4; j++) {
            float4 f = __ldcs(p + j);
            v[4 * j + 0] = f.x;
            v[4 * j + 1] = f.y;
            v[4 * j + 2] = f.z;
            v[4 * j + 3] = f.w;
        }
    }

    // H16 over n0
    h16(v);

    // ---- Phase A: thread (n2 = t>>4, n1 = t&15) scatters 4x STS.128 ----
    {
        const int n1 = t & 15;
        const int c  = (n1 >> 1) & 3;
        float4* b4 = reinterpret_cast<float4*>(s + (t >> 4) * 272 + n1 * 16);
#pragma unroll
        for (int a = 0; a < 4; a++)
            b4[a ^ c] = make_float4(v[4 * a], v[4 * a + 1],
                                    v[4 * a + 2], v[4 * a + 3]);
    }
    __syncwarp();   // exchange A is within a half-warp (n2-group)

    // ---- Phase B: thread (n2 = t>>4, n0 = t&15) gathers n1 = k ----
    {
        const int n0 = t & 15;
        const int g  = n0 >> 2;
        // addr(k) = n2*272 + 16k + 4*(g ^ ((k>>1)&3)) + (n0&3)
        float* base = s + (t >> 4) * 272 + (n0 & 3);
#pragma unroll
        for (int k = 0; k < 16; k++)
            v[k] = base[16 * k + 4 * (g ^ ((k >> 1) & 3))];

        h16(v);   // H16 over n1

#pragma unroll
        for (int k = 0; k < 16; k++)
            base[16 * k + 4 * (g ^ ((k >> 1) & 3))] = v[k];
    }
    __syncthreads();   // exchange B crosses the whole CTA

    // ---- Phase C: thread (n1' = t>>4, n0' = t&15) gathers n2 = k ----
    {
        const int n1 = t >> 4;
        const int n0 = t & 15;
        const float* base = s + n1 * 16
                              + 4 * ((n0 >> 2) ^ ((n1 >> 1) & 3)) + (n0 & 3);
#pragma unroll
        for (int k = 0; k < 16; k++)
            v[k] = base[272 * k];

        h16(v);   // H16 over n2

        const float sc = 0.015625f;   // 1/64
        float* __restrict__ yr = y + row + 16 * n1 + n0;
#pragma unroll
        for (int k = 0; k < 16; k++)
            __stcs(yr + 256 * k, v[k] * sc);   // 128B-coalesced per warp instr
    }
}

extern "C" void kernel_launch(void* const* d_in, const int* in_sizes, int n_in,
                              void* d_out, int out_size) {
    (void)n_in; (void)out_size;
    const float* x = (const float*)d_in[0];
    float* y = (float*)d_out;
    const int rows = in_sizes[0] / FWHT_DIM;   // 16384
    fwht4096_kernel<<<rows, 256>>>(x, y);
}

// round 10
// speedup vs baseline: 1.0945x; 1.0897x over previous
#include <cuda_runtime.h>

// FWHT, DIM=4096, fp32, scale 1/64. Three in-register H16 passes over bit
// groups {b0,b1,b10,b11} / {b2..b5} / {b6..b9} (stages on disjoint bits
// commute), two smem exchanges. One CTA (256 thr) per row, 16 floats/thread.
//
// Coalesced I/O: thread t loads float4 chunks t+256j (4 wf per LDG.128 warp
// instruction); final stores are warp-contiguous STG.32 (1 wf each).
//
// Smem: 4096 words (16 KB), XOR swizzle P(e) = e ^ ((e>>4) & 0x1C)
// (bits b6,b7,b8 XORed into b2,b3,b4). Bank = (b0,b1,b2^b6,b3^b7,b4^b8).
// All four smem phases are 32-distinct-bank per warp instruction:
//  W1 STS.128: quarter-warp varies b2b3b4 -> distinct chunk-banks
//  R1/W2 scalar: warp varies b0,b1,b6,b7,b8 -> bank bijective
//  R2 scalar:   warp varies b0..b4 -> bank bijective

#define FWHT_DIM 4096

__device__ __forceinline__ void h16(float (&v)[16]) {
#pragma unroll
    for (int h = 1; h < 16; h <<= 1) {
#pragma unroll
        for (int i = 0; i < 16; i++) {
            if (!(i & h)) {
                float a = v[i];
                float b = v[i + h];
                v[i]     = a + b;
                v[i + h] = a - b;
            }
        }
    }
}

__global__ __launch_bounds__(256)
void fwht4096_kernel(const float* __restrict__ x, float* __restrict__ y) {
    __shared__ float s[4096];   // 16 KB, swizzled

    const int t = threadIdx.x;                    // 0..255
    const size_t row = (size_t)blockIdx.x * FWHT_DIM;

    float v[16];

    // ---- Load: lane-contiguous LDG.128. v[4j+c] = element (j<<10)|(t<<2)|c
    //      -> regs own bits {b0,b1,b10,b11}, lanes own b2..b9. ----
    {
        const float4* __restrict__ p = reinterpret_cast<const float4*>(x + row);
#pragma unroll
        for (int j = 0; j < 4; j++) {
            float4 f = __ldcs(p + t + 256 * j);
            v[4 * j + 0] = f.x;
            v[4 * j + 1] = f.y;
            v[4 * j + 2] = f.z;
            v[4 * j + 3] = f.w;
        }
    }

    h16(v);   // H16 over bits {b0,b1,b10,b11}

    // ---- W1: 4x STS.128. Chunk q = j*256 + t; swizzled chunk = j*256 + (t ^ ((t>>4)&7)) ----
    {
        float4* s4 = reinterpret_cast<float4*>(s);
        const int tc = t ^ ((t >> 4) & 7);
#pragma unroll
        for (int j = 0; j < 4; j++)
            s4[j * 256 + tc] = make_float4(v[4 * j], v[4 * j + 1],
                                           v[4 * j + 2], v[4 * j + 3]);
    }
    __syncthreads();

    // ---- Pass 2: thread u=t owns fixed (b0,b1,b6..b11) = ((t&3), (t>>2)<<6),
    //      regs m = b5b4b3b2. e = base + 4m, P = base + 4*(m ^ sb), sb=b6b7b8. ----
    {
        const int base = (t & 3) | ((t & 0xFC) << 4);
        const int sb   = (t >> 2) & 7;
#pragma unroll
        for (int m = 0; m < 16; m++)
            v[m] = s[base + 4 * (m ^ sb)];

        h16(v);   // H16 over bits {b2..b5}

#pragma unroll
        for (int m = 0; m < 16; m++)
            s[base + 4 * (m ^ sb)] = v[m];
    }
    __syncthreads();

    // ---- Pass 3: thread w=t owns fixed (b0..b5,b10,b11) = ((t&63), (t>>6)<<10),
    //      regs k = b9b8b7b6. e = basew + 64k, P = e ^ ((k&7)<<2). ----
    {
        const int basew = (t & 63) | ((t & 0xC0) << 4);
#pragma unroll
        for (int k = 0; k < 16; k++)
            v[k] = s[(basew + 64 * k) ^ ((k & 7) << 2)];

        h16(v);   // H16 over bits {b6..b9}

        const float sc = 0.015625f;   // 1/64 = 1/sqrt(4096)
        float* __restrict__ yr = y + row + basew;
#pragma unroll
        for (int k = 0; k < 16; k++)
            __stcs(yr + 64 * k, v[k] * sc);   // warp-contiguous, 1 wf each
    }
}

extern "C" void kernel_launch(void* const* d_in, const int* in_sizes, int n_in,
                              void* d_out, int out_size) {
    (void)n_in; (void)out_size;
    const float* x = (const float*)d_in[0];
    float* y = (float*)d_out;
    const int rows = in_sizes[0] / FWHT_DIM;   // 16384
    fwht4096_kernel<<<rows, 256>>>(x, y);
}